// round 5
// baseline (speedup 1.0000x reference)
#include <cuda_runtime.h>
#include <cuda_bf16.h>
#include <math.h>

#define N_NODES 50000
#define N_EDGES 800000
#define HID 16

// ---------------- device scratch (module-static, allowed) ----------------
__device__ int    g_src[N_EDGES];
__device__ int    g_dst[N_EDGES];
__device__ int    g_asrc[N_EDGES];
__device__ int    g_adst[N_EDGES];
__device__ float2 g_arel[N_EDGES];
__device__ int    g_M;
__device__ int    g_cnt[N_NODES];
__device__ float  g_cntinv[N_NODES];
__device__ float  g_h0[N_NODES * HID];
__device__ float  g_h1[N_NODES * HID];
__device__ float  g_agg[N_NODES * HID];
__device__ int    g_is64_ei;
__device__ int    g_is64_rg;

// ---------------- kernels ----------------

// detect int64 vs int32 layout: for int64 little-endian values < 2^31,
// every odd 32-bit word is zero. For int32 random node ids, essentially never.
__global__ void k_detect(const int* __restrict__ ei, const int* __restrict__ rg) {
    if (blockIdx.x == 0 && threadIdx.x == 0) {
        int all0 = 1;
        for (int i = 0; i < 32; i++) if (ei[2 * i + 1] != 0) { all0 = 0; break; }
        g_is64_ei = all0;
        all0 = 1;
        for (int i = 0; i < 32; i++) if (rg[2 * i + 1] != 0) { all0 = 0; break; }
        g_is64_rg = all0;
    }
}

__global__ void k_zero_cnt() {
    int i = blockIdx.x * blockDim.x + threadIdx.x;
    if (i < N_NODES) g_cnt[i] = 0;
    if (i == 0) g_M = 0;
}

__global__ void k_zero_agg() {
    int i = blockIdx.x * blockDim.x + threadIdx.x;
    if (i < N_NODES * HID) g_agg[i] = 0.0f;
}

// count in-degree, compact same-region edges + rel (dtype-robust indexing)
__global__ void k_setup(const int* __restrict__ ei,
                        const int* __restrict__ region,
                        const float* __restrict__ x) {
    int e = blockIdx.x * blockDim.x + threadIdx.x;
    if (e >= N_EDGES) return;
    int is64e = g_is64_ei;
    int is64r = g_is64_rg;
    int s, d;
    if (is64e) {
        s = ei[2 * e];
        d = ei[2 * (N_EDGES + e)];
    } else {
        s = ei[e];
        d = ei[N_EDGES + e];
    }
    g_src[e] = s;
    g_dst[e] = d;
    atomicAdd(&g_cnt[d], 1);
    int rs = is64r ? region[2 * s] : region[s];
    int rd = is64r ? region[2 * d] : region[d];
    if (rs == rd) {
        int i = atomicAdd(&g_M, 1);
        g_asrc[i] = s;
        g_adst[i] = d;
        float2 r;
        r.x = x[d * 16 + 0] - x[s * 16 + 0];
        r.y = x[d * 16 + 1] - x[s * 16 + 1];
        g_arel[i] = r;
    }
}

__global__ void k_cntinv() {
    int n = blockIdx.x * blockDim.x + threadIdx.x;
    if (n < N_NODES) g_cntinv[n] = 1.0f / fmaxf((float)g_cnt[n], 1.0f);
}

__device__ __forceinline__ void red_add_v4(float* p, float a, float b, float c, float d) {
    asm volatile("red.global.add.v4.f32 [%0], {%1, %2, %3, %4};"
                 :: "l"(p), "f"(a), "f"(b), "f"(c), "f"(d) : "memory");
}

// per active edge: spatial = relu(rel@W_in+b_in), msg = h[src]^T spatial, scatter
template <int IC>
__global__ void k_edge(const float* __restrict__ hbase, int hstride,
                       const float* __restrict__ W, const float* __restrict__ b) {
    __shared__ float sW0[IC * HID];
    __shared__ float sW1[IC * HID];
    __shared__ float sB[IC * HID];
    for (int i = threadIdx.x; i < IC * HID; i += blockDim.x) {
        sW0[i] = W[i];
        sW1[i] = W[IC * HID + i];
        sB[i]  = b[i];
    }
    __syncthreads();
    const int M = g_M;
    for (int e = blockIdx.x * blockDim.x + threadIdx.x; e < M;
         e += gridDim.x * blockDim.x) {
        int s = g_asrc[e];
        int d = g_adst[e];
        float2 r = g_arel[e];
        const float* __restrict__ h = hbase + (long)s * hstride;
        float acc[HID];
#pragma unroll
        for (int j = 0; j < HID; j++) acc[j] = 0.0f;
        for (int c = 0; c < IC; c++) {
            float hc = h[c];
#pragma unroll
            for (int j = 0; j < HID; j++) {
                float sp = fmaf(r.x, sW0[c * HID + j],
                            fmaf(r.y, sW1[c * HID + j], sB[c * HID + j]));
                sp = fmaxf(sp, 0.0f);
                acc[j] = fmaf(hc, sp, acc[j]);
            }
        }
        float* a = &g_agg[(long)d * HID];
#pragma unroll
        for (int q = 0; q < 4; q++)
            red_add_v4(a + q * 4, acc[q * 4 + 0], acc[q * 4 + 1],
                       acc[q * 4 + 2], acc[q * 4 + 3]);
    }
}

// h_out = relu((agg * cntinv) @ W_out + b_out); re-zero agg for next layer
__global__ void k_node(const float* __restrict__ Wout,
                       const float* __restrict__ bout,
                       float* __restrict__ hout) {
    __shared__ float sW[HID * HID];
    __shared__ float sB[HID];
    for (int i = threadIdx.x; i < HID * HID; i += blockDim.x) sW[i] = Wout[i];
    if (threadIdx.x < HID) sB[threadIdx.x] = bout[threadIdx.x];
    __syncthreads();
    int n = blockIdx.x * blockDim.x + threadIdx.x;
    if (n >= N_NODES) return;
    float inv = g_cntinv[n];
    float a[HID];
    float4* ag = (float4*)&g_agg[(long)n * HID];
    const float4 zero4 = make_float4(0.f, 0.f, 0.f, 0.f);
#pragma unroll
    for (int q = 0; q < 4; q++) {
        float4 v = ag[q];
        a[q * 4 + 0] = v.x * inv;
        a[q * 4 + 1] = v.y * inv;
        a[q * 4 + 2] = v.z * inv;
        a[q * 4 + 3] = v.w * inv;
        ag[q] = zero4;  // fused zeroing for next layer's scatter
    }
    float* ho = hout + (long)n * HID;
#pragma unroll
    for (int j = 0; j < HID; j++) {
        float o = sB[j];
#pragma unroll
        for (int k = 0; k < HID; k++) o = fmaf(a[k], sW[k * HID + j], o);
        ho[j] = fmaxf(o, 0.0f);
    }
}

// decoder: z=[h[src],h[dst]]; relu MLPs; sigmoid
__global__ void k_decoder(const float* __restrict__ h,
                          const float* __restrict__ Wd1, const float* __restrict__ bd1,
                          const float* __restrict__ Wd2, const float* __restrict__ bd2,
                          const float* __restrict__ Wd3, const float* __restrict__ bd3,
                          float* __restrict__ out) {
    __shared__ float sW1[32 * HID];
    __shared__ float sB1[HID];
    __shared__ float sW2[HID * HID];
    __shared__ float sB2[HID];
    __shared__ float sW3[HID];
    __shared__ float sB3;
    for (int i = threadIdx.x; i < 32 * HID; i += blockDim.x) sW1[i] = Wd1[i];
    for (int i = threadIdx.x; i < HID * HID; i += blockDim.x) sW2[i] = Wd2[i];
    if (threadIdx.x < HID) {
        sB1[threadIdx.x] = bd1[threadIdx.x];
        sB2[threadIdx.x] = bd2[threadIdx.x];
        sW3[threadIdx.x] = Wd3[threadIdx.x];
    }
    if (threadIdx.x == 0) sB3 = bd3[0];
    __syncthreads();
    int e = blockIdx.x * blockDim.x + threadIdx.x;
    if (e >= N_EDGES) return;
    int s = g_src[e];
    int d = g_dst[e];
    float z[32];
    const float4* hs = (const float4*)(h + (long)s * HID);
    const float4* hd = (const float4*)(h + (long)d * HID);
#pragma unroll
    for (int q = 0; q < 4; q++) {
        float4 v = hs[q];
        z[q * 4 + 0] = v.x; z[q * 4 + 1] = v.y; z[q * 4 + 2] = v.z; z[q * 4 + 3] = v.w;
    }
#pragma unroll
    for (int q = 0; q < 4; q++) {
        float4 v = hd[q];
        z[16 + q * 4 + 0] = v.x; z[16 + q * 4 + 1] = v.y;
        z[16 + q * 4 + 2] = v.z; z[16 + q * 4 + 3] = v.w;
    }
    float t1[HID];
#pragma unroll
    for (int j = 0; j < HID; j++) {
        float o = sB1[j];
#pragma unroll
        for (int k = 0; k < 32; k++) o = fmaf(z[k], sW1[k * HID + j], o);
        t1[j] = fmaxf(o, 0.0f);
    }
    float t2[HID];
#pragma unroll
    for (int j = 0; j < HID; j++) {
        float o = sB2[j];
#pragma unroll
        for (int k = 0; k < HID; k++) o = fmaf(t1[k], sW2[k * HID + j], o);
        t2[j] = fmaxf(o, 0.0f);
    }
    float o = sB3;
#pragma unroll
    for (int k = 0; k < HID; k++) o = fmaf(t2[k], sW3[k], o);
    out[e] = 1.0f / (1.0f + expf(-o));
}

// ---------------- launch ----------------
extern "C" void kernel_launch(void* const* d_in, const int* in_sizes, int n_in,
                              void* d_out, int out_size) {
    const float* x      = (const float*)d_in[0];
    const int*   ei     = (const int*)d_in[1];
    const int*   region = (const int*)d_in[2];
    const float* W_in1  = (const float*)d_in[3];
    const float* b_in1  = (const float*)d_in[4];
    const float* W_out1 = (const float*)d_in[5];
    const float* b_out1 = (const float*)d_in[6];
    const float* W_in2  = (const float*)d_in[7];
    const float* b_in2  = (const float*)d_in[8];
    const float* W_out2 = (const float*)d_in[9];
    const float* b_out2 = (const float*)d_in[10];
    const float* W_in3  = (const float*)d_in[11];
    const float* b_in3  = (const float*)d_in[12];
    const float* W_out3 = (const float*)d_in[13];
    const float* b_out3 = (const float*)d_in[14];
    const float* Wd1 = (const float*)d_in[15];
    const float* bd1 = (const float*)d_in[16];
    const float* Wd2 = (const float*)d_in[17];
    const float* bd2 = (const float*)d_in[18];
    const float* Wd3 = (const float*)d_in[19];
    const float* bd3 = (const float*)d_in[20];
    float* out = (float*)d_out;

    float *h0, *h1;
    cudaGetSymbolAddress((void**)&h0, g_h0);
    cudaGetSymbolAddress((void**)&h1, g_h1);

    const int TB = 256;
    const int gN   = (N_NODES + TB - 1) / TB;
    const int gE   = (N_EDGES + TB - 1) / TB;
    const int gNH  = (N_NODES * HID + TB - 1) / TB;
    const int gEdge = 592;  // grid-stride persistent over active edges

    k_detect<<<1, 32>>>(ei, region);
    k_zero_cnt<<<gN, TB>>>();
    k_zero_agg<<<gNH, TB>>>();   // only needed once; k_node re-zeros thereafter
    k_setup<<<gE, TB>>>(ei, region, x);
    k_cntinv<<<gN, TB>>>();

    // layer 1: h input = x[:,2:] (stride 16, 14 channels)
    k_edge<14><<<gEdge, TB>>>(x + 2, 16, W_in1, b_in1);
    k_node<<<gN, TB>>>(W_out1, b_out1, h0);

    // layer 2
    k_edge<16><<<gEdge, TB>>>(h0, HID, W_in2, b_in2);
    k_node<<<gN, TB>>>(W_out2, b_out2, h1);

    // layer 3
    k_edge<16><<<gEdge, TB>>>(h1, HID, W_in3, b_in3);
    k_node<<<gN, TB>>>(W_out3, b_out3, h0);

    // decoder
    k_decoder<<<gE, TB>>>(h0, Wd1, bd1, Wd2, bd2, Wd3, bd3, out);
}

// round 11
// speedup vs baseline: 1.1844x; 1.1844x over previous
#include <cuda_runtime.h>
#include <cuda_bf16.h>
#include <math.h>

#define N_NODES 50000
#define N_EDGES 800000
#define HID 16

// ---------------- device scratch (zero-initialized at module load) ----------------
__device__ int    g_src[N_EDGES];
__device__ int    g_dst[N_EDGES];
__device__ int    g_asrc[N_EDGES];
__device__ int    g_adst[N_EDGES];
__device__ float2 g_arel[N_EDGES];
__device__ int    g_M;
__device__ int    g_cnt[N_NODES];          // invariant: zero at launch entry
__device__ float  g_cntinv[N_NODES];
__device__ __align__(16) float g_h0[N_NODES * HID];
__device__ __align__(16) float g_h1[N_NODES * HID];
__device__ __align__(16) float g_agg[N_NODES * HID];   // invariant: zero at entry
__device__ __align__(16) float g_P[N_NODES * 32];      // per-node decoder projections
__device__ int    g_is64_ei;
__device__ int    g_is64_rg;

// ---------------- kernels ----------------

// detect int64 vs int32 layout: for int64 little-endian values < 2^31,
// every odd 32-bit word is zero. For int32 random node ids, essentially never.
__global__ void k_detect(const int* __restrict__ ei, const int* __restrict__ rg) {
    if (blockIdx.x == 0 && threadIdx.x == 0) {
        int all0 = 1;
        for (int i = 0; i < 32; i++) if (ei[2 * i + 1] != 0) { all0 = 0; break; }
        g_is64_ei = all0;
        all0 = 1;
        for (int i = 0; i < 32; i++) if (rg[2 * i + 1] != 0) { all0 = 0; break; }
        g_is64_rg = all0;
    }
}

// count in-degree, compact same-region edges (warp-aggregated counter) + rel
__global__ void k_setup(const int* __restrict__ ei,
                        const int* __restrict__ region,
                        const float* __restrict__ x) {
    int e = blockIdx.x * blockDim.x + threadIdx.x;   // grid sized exactly
    int is64e = g_is64_ei;
    int is64r = g_is64_rg;
    int s, d;
    if (is64e) {
        s = ei[2 * e];
        d = ei[2 * (N_EDGES + e)];
    } else {
        s = ei[e];
        d = ei[N_EDGES + e];
    }
    g_src[e] = s;
    g_dst[e] = d;
    atomicAdd(&g_cnt[d], 1);
    int rs = is64r ? region[2 * s] : region[s];
    int rd = is64r ? region[2 * d] : region[d];
    bool active = (rs == rd);
    unsigned mask = __ballot_sync(0xffffffffu, active);
    if (active) {
        int lane = threadIdx.x & 31;
        int leader = __ffs(mask) - 1;
        int base = 0;
        if (lane == leader) base = atomicAdd(&g_M, __popc(mask));
        base = __shfl_sync(mask, base, leader);
        int i = base + __popc(mask & ((1u << lane) - 1u));
        g_asrc[i] = s;
        g_adst[i] = d;
        float2 r;
        r.x = x[d * 16 + 0] - x[s * 16 + 0];
        r.y = x[d * 16 + 1] - x[s * 16 + 1];
        g_arel[i] = r;
    }
}

// cnt -> 1/max(cnt,1), and restore cnt=0 for next replay
__global__ void k_cntinv() {
    int n = blockIdx.x * blockDim.x + threadIdx.x;
    if (n < N_NODES) {
        g_cntinv[n] = 1.0f / fmaxf((float)g_cnt[n], 1.0f);
        g_cnt[n] = 0;
    }
}

__device__ __forceinline__ void red_add_v4(float* p, float a, float b, float c, float d) {
    asm volatile("red.global.add.v4.f32 [%0], {%1, %2, %3, %4};"
                 :: "l"(p), "f"(a), "f"(b), "f"(c), "f"(d) : "memory");
}

// per active edge: spatial = relu(rel@W_in+b_in), msg = h[src]^T spatial, scatter
// VEC=1: h rows are 16B-aligned, load via float4 (requires IC==16)
template <int IC, int VEC>
__global__ void k_edge(const float* __restrict__ hbase, int hstride,
                       const float* __restrict__ W, const float* __restrict__ b) {
    __shared__ float sW0[IC * HID];
    __shared__ float sW1[IC * HID];
    __shared__ float sB[IC * HID];
    for (int i = threadIdx.x; i < IC * HID; i += blockDim.x) {
        sW0[i] = W[i];
        sW1[i] = W[IC * HID + i];
        sB[i]  = b[i];
    }
    __syncthreads();
    const int M = g_M;
    for (int e = blockIdx.x * blockDim.x + threadIdx.x; e < M;
         e += gridDim.x * blockDim.x) {
        int s = g_asrc[e];
        int d = g_adst[e];
        float2 r = g_arel[e];
        const float* __restrict__ h = hbase + (long)s * hstride;
        float hv[IC];
        if (VEC) {
            const float4* h4 = (const float4*)h;
#pragma unroll
            for (int q = 0; q < IC / 4; q++) {
                float4 v = h4[q];
                hv[q * 4 + 0] = v.x; hv[q * 4 + 1] = v.y;
                hv[q * 4 + 2] = v.z; hv[q * 4 + 3] = v.w;
            }
        } else {
#pragma unroll
            for (int c = 0; c < IC; c++) hv[c] = h[c];
        }
        float acc[HID];
#pragma unroll
        for (int j = 0; j < HID; j++) acc[j] = 0.0f;
#pragma unroll
        for (int c = 0; c < IC; c++) {
            float hc = hv[c];
#pragma unroll
            for (int j = 0; j < HID; j++) {
                float sp = fmaf(r.x, sW0[c * HID + j],
                            fmaf(r.y, sW1[c * HID + j], sB[c * HID + j]));
                sp = fmaxf(sp, 0.0f);
                acc[j] = fmaf(hc, sp, acc[j]);
            }
        }
        float* a = &g_agg[(long)d * HID];
#pragma unroll
        for (int q = 0; q < 4; q++)
            red_add_v4(a + q * 4, acc[q * 4 + 0], acc[q * 4 + 1],
                       acc[q * 4 + 2], acc[q * 4 + 3]);
    }
}

// h_out = relu((agg * cntinv) @ W_out + b_out); re-zero agg for next layer
__global__ void k_node(const float* __restrict__ Wout,
                       const float* __restrict__ bout,
                       float* __restrict__ hout) {
    __shared__ float sW[HID * HID];
    __shared__ float sB[HID];
    for (int i = threadIdx.x; i < HID * HID; i += blockDim.x) sW[i] = Wout[i];
    if (threadIdx.x < HID) sB[threadIdx.x] = bout[threadIdx.x];
    __syncthreads();
    int n = blockIdx.x * blockDim.x + threadIdx.x;
    if (n >= N_NODES) return;
    float inv = g_cntinv[n];
    float a[HID];
    float4* ag = (float4*)&g_agg[(long)n * HID];
    const float4 zero4 = make_float4(0.f, 0.f, 0.f, 0.f);
#pragma unroll
    for (int q = 0; q < 4; q++) {
        float4 v = ag[q];
        a[q * 4 + 0] = v.x * inv;
        a[q * 4 + 1] = v.y * inv;
        a[q * 4 + 2] = v.z * inv;
        a[q * 4 + 3] = v.w * inv;
        ag[q] = zero4;
    }
    float* ho = hout + (long)n * HID;
#pragma unroll
    for (int j = 0; j < HID; j++) {
        float o = sB[j];
#pragma unroll
        for (int k = 0; k < HID; k++) o = fmaf(a[k], sW[k * HID + j], o);
        ho[j] = fmaxf(o, 0.0f);
    }
}

// layer-3 node MLP fused with decoder pre-projection:
// h = relu((agg*inv)@Wout+b); P[n][0:16]=h@Wd1[0:16,:]; P[n][16:32]=h@Wd1[16:32,:]
__global__ void k_node_pre(const float* __restrict__ Wout,
                           const float* __restrict__ bout,
                           const float* __restrict__ Wd1) {
    __shared__ float sW[HID * HID];
    __shared__ float sB[HID];
    __shared__ float sD[32 * HID];
    for (int i = threadIdx.x; i < HID * HID; i += blockDim.x) sW[i] = Wout[i];
    for (int i = threadIdx.x; i < 32 * HID; i += blockDim.x) sD[i] = Wd1[i];
    if (threadIdx.x < HID) sB[threadIdx.x] = bout[threadIdx.x];
    __syncthreads();
    int n = blockIdx.x * blockDim.x + threadIdx.x;
    if (blockIdx.x == 0 && threadIdx.x == 0) g_M = 0;  // reset compaction counter
    if (n >= N_NODES) return;
    float inv = g_cntinv[n];
    float a[HID];
    float4* ag = (float4*)&g_agg[(long)n * HID];
    const float4 zero4 = make_float4(0.f, 0.f, 0.f, 0.f);
#pragma unroll
    for (int q = 0; q < 4; q++) {
        float4 v = ag[q];
        a[q * 4 + 0] = v.x * inv;
        a[q * 4 + 1] = v.y * inv;
        a[q * 4 + 2] = v.z * inv;
        a[q * 4 + 3] = v.w * inv;
        ag[q] = zero4;
    }
    float hres[HID];
#pragma unroll
    for (int j = 0; j < HID; j++) {
        float o = sB[j];
#pragma unroll
        for (int k = 0; k < HID; k++) o = fmaf(a[k], sW[k * HID + j], o);
        hres[j] = fmaxf(o, 0.0f);
    }
    float* P = &g_P[(long)n * 32];
#pragma unroll
    for (int j = 0; j < HID; j++) {
        float t = 0.0f, u = 0.0f;
#pragma unroll
        for (int k = 0; k < HID; k++) {
            t = fmaf(hres[k], sD[k * HID + j], t);           // Wd1 rows 0..15
            u = fmaf(hres[k], sD[(HID + k) * HID + j], u);   // Wd1 rows 16..31
        }
        P[j] = t;
        P[HID + j] = u;
    }
}

// decoder: t1 = relu(Ptop[s] + Pbot[d] + b1); relu MLP; sigmoid
__global__ void k_decoder(const float* __restrict__ bd1,
                          const float* __restrict__ Wd2, const float* __restrict__ bd2,
                          const float* __restrict__ Wd3, const float* __restrict__ bd3,
                          float* __restrict__ out) {
    __shared__ float sB1[HID];
    __shared__ float sW2[HID * HID];
    __shared__ float sB2[HID];
    __shared__ float sW3[HID];
    __shared__ float sB3;
    for (int i = threadIdx.x; i < HID * HID; i += blockDim.x) sW2[i] = Wd2[i];
    if (threadIdx.x < HID) {
        sB1[threadIdx.x] = bd1[threadIdx.x];
        sB2[threadIdx.x] = bd2[threadIdx.x];
        sW3[threadIdx.x] = Wd3[threadIdx.x];
    }
    if (threadIdx.x == 0) sB3 = bd3[0];
    __syncthreads();
    int e = blockIdx.x * blockDim.x + threadIdx.x;
    int s = g_src[e];
    int d = g_dst[e];
    const float4* ps = (const float4*)&g_P[(long)s * 32];        // top half
    const float4* pd = (const float4*)&g_P[(long)d * 32 + HID];  // bottom half
    float t1[HID];
#pragma unroll
    for (int q = 0; q < 4; q++) {
        float4 va = ps[q];
        float4 vb = pd[q];
        t1[q * 4 + 0] = fmaxf(va.x + vb.x + sB1[q * 4 + 0], 0.0f);
        t1[q * 4 + 1] = fmaxf(va.y + vb.y + sB1[q * 4 + 1], 0.0f);
        t1[q * 4 + 2] = fmaxf(va.z + vb.z + sB1[q * 4 + 2], 0.0f);
        t1[q * 4 + 3] = fmaxf(va.w + vb.w + sB1[q * 4 + 3], 0.0f);
    }
    float t2[HID];
#pragma unroll
    for (int j = 0; j < HID; j++) {
        float o = sB2[j];
#pragma unroll
        for (int k = 0; k < HID; k++) o = fmaf(t1[k], sW2[k * HID + j], o);
        t2[j] = fmaxf(o, 0.0f);
    }
    float o = sB3;
#pragma unroll
    for (int k = 0; k < HID; k++) o = fmaf(t2[k], sW3[k], o);
    out[e] = 1.0f / (1.0f + __expf(-o));
}

// ---------------- launch ----------------
extern "C" void kernel_launch(void* const* d_in, const int* in_sizes, int n_in,
                              void* d_out, int out_size) {
    const float* x      = (const float*)d_in[0];
    const int*   ei     = (const int*)d_in[1];
    const int*   region = (const int*)d_in[2];
    const float* W_in1  = (const float*)d_in[3];
    const float* b_in1  = (const float*)d_in[4];
    const float* W_out1 = (const float*)d_in[5];
    const float* b_out1 = (const float*)d_in[6];
    const float* W_in2  = (const float*)d_in[7];
    const float* b_in2  = (const float*)d_in[8];
    const float* W_out2 = (const float*)d_in[9];
    const float* b_out2 = (const float*)d_in[10];
    const float* W_in3  = (const float*)d_in[11];
    const float* b_in3  = (const float*)d_in[12];
    const float* W_out3 = (const float*)d_in[13];
    const float* b_out3 = (const float*)d_in[14];
    const float* Wd1 = (const float*)d_in[15];
    const float* bd1 = (const float*)d_in[16];
    const float* Wd2 = (const float*)d_in[17];
    const float* bd2 = (const float*)d_in[18];
    const float* Wd3 = (const float*)d_in[19];
    const float* bd3 = (const float*)d_in[20];
    float* out = (float*)d_out;

    float *h0, *h1;
    cudaGetSymbolAddress((void**)&h0, g_h0);
    cudaGetSymbolAddress((void**)&h1, g_h1);

    const int TB = 256;
    const int gN   = (N_NODES + TB - 1) / TB;
    const int gE   = N_EDGES / TB;          // exact: 800000/256 = 3125
    const int gEdge = 592;                  // grid-stride over active edges

    k_detect<<<1, 32>>>(ei, region);
    k_setup<<<gE, TB>>>(ei, region, x);
    k_cntinv<<<gN, TB>>>();

    // layer 1: h input = x[:,2:] (stride 16, 14 channels, misaligned -> scalar)
    k_edge<14, 0><<<gEdge, TB>>>(x + 2, 16, W_in1, b_in1);
    k_node<<<gN, TB>>>(W_out1, b_out1, h0);

    // layer 2 (h0 rows 64B-aligned -> float4 gathers)
    k_edge<16, 1><<<gEdge, TB>>>(h0, HID, W_in2, b_in2);
    k_node<<<gN, TB>>>(W_out2, b_out2, h1);

    // layer 3 fused with decoder pre-projection
    k_edge<16, 1><<<gEdge, TB>>>(h1, HID, W_in3, b_in3);
    k_node_pre<<<gN, TB>>>(W_out3, b_out3, Wd1);

    // decoder
    k_decoder<<<gE, TB>>>(bd1, Wd2, bd2, Wd3, bd3, out);
}

// round 12
// speedup vs baseline: 1.1885x; 1.0034x over previous
#include <cuda_runtime.h>
#include <cuda_bf16.h>
#include <math.h>

#define N_NODES 50000
#define N_EDGES 800000
#define HID 16

// ---------------- device scratch (zero-initialized at module load) ----------------
__device__ int2   g_sd[N_EDGES];                         // packed (src,dst) for decoder
__device__ __align__(16) float4 g_aedge[N_EDGES];        // packed active edge {s,d,rx,ry}
__device__ int    g_M;
__device__ int    g_cnt[N_NODES];          // invariant: zero at launch entry
__device__ float  g_cntinv[N_NODES];
__device__ __align__(16) float g_hin[N_NODES * HID];     // staged layer-1 features
__device__ __align__(16) float g_h0[N_NODES * HID];
__device__ __align__(16) float g_h1[N_NODES * HID];
__device__ __align__(16) float g_agg[N_NODES * HID];     // invariant: zero at entry
__device__ __align__(16) float g_P[N_NODES * 32];        // per-node decoder projections
__device__ int    g_is64_ei;
__device__ int    g_is64_rg;

// ---------------- kernels ----------------

// detect int64 vs int32 layout: for int64 little-endian values < 2^31,
// every odd 32-bit word is zero. For int32 random node ids, essentially never.
__global__ void k_detect(const int* __restrict__ ei, const int* __restrict__ rg) {
    if (blockIdx.x == 0 && threadIdx.x == 0) {
        int all0 = 1;
        for (int i = 0; i < 32; i++) if (ei[2 * i + 1] != 0) { all0 = 0; break; }
        g_is64_ei = all0;
        all0 = 1;
        for (int i = 0; i < 32; i++) if (rg[2 * i + 1] != 0) { all0 = 0; break; }
        g_is64_rg = all0;
    }
}

// count in-degree, compact same-region edges (warp-aggregated counter) + rel
__global__ void k_setup(const int* __restrict__ ei,
                        const int* __restrict__ region,
                        const float* __restrict__ x) {
    int e = blockIdx.x * blockDim.x + threadIdx.x;   // grid sized exactly
    int is64e = g_is64_ei;
    int is64r = g_is64_rg;
    int s, d;
    if (is64e) {
        s = ei[2 * e];
        d = ei[2 * (N_EDGES + e)];
    } else {
        s = ei[e];
        d = ei[N_EDGES + e];
    }
    g_sd[e] = make_int2(s, d);
    atomicAdd(&g_cnt[d], 1);
    int rs = is64r ? region[2 * s] : region[s];
    int rd = is64r ? region[2 * d] : region[d];
    bool active = (rs == rd);
    unsigned mask = __ballot_sync(0xffffffffu, active);
    if (active) {
        int lane = threadIdx.x & 31;
        int leader = __ffs(mask) - 1;
        int base = 0;
        if (lane == leader) base = atomicAdd(&g_M, __popc(mask));
        base = __shfl_sync(mask, base, leader);
        int i = base + __popc(mask & ((1u << lane) - 1u));
        float4 rec;
        rec.x = __int_as_float(s);
        rec.y = __int_as_float(d);
        rec.z = x[d * 16 + 0] - x[s * 16 + 0];
        rec.w = x[d * 16 + 1] - x[s * 16 + 1];
        g_aedge[i] = rec;
    }
}

// cnt -> 1/max(cnt,1) (restore cnt=0), and stage layer-1 features:
// g_hin[n][c] = x[n][2+c] for c<14, 0 for c=14,15  (aligned 64B rows)
__global__ void k_cntinv(const float* __restrict__ x) {
    int n = blockIdx.x * blockDim.x + threadIdx.x;
    if (n >= N_NODES) return;
    g_cntinv[n] = 1.0f / fmaxf((float)g_cnt[n], 1.0f);
    g_cnt[n] = 0;
    const float4* xr = (const float4*)(x + (long)n * 16);
    float4 v0 = xr[0], v1 = xr[1], v2 = xr[2], v3 = xr[3];
    float4* ho = (float4*)&g_hin[(long)n * HID];
    ho[0] = make_float4(v0.z, v0.w, v1.x, v1.y);
    ho[1] = make_float4(v1.z, v1.w, v2.x, v2.y);
    ho[2] = make_float4(v2.z, v2.w, v3.x, v3.y);
    ho[3] = make_float4(v3.z, v3.w, 0.0f, 0.0f);
}

__device__ __forceinline__ void red_add_v4(float* p, float a, float b, float c, float d) {
    asm volatile("red.global.add.v4.f32 [%0], {%1, %2, %3, %4};"
                 :: "l"(p), "f"(a), "f"(b), "f"(c), "f"(d) : "memory");
}

// per active edge: spatial = relu(rel@W_in+b_in), msg = h[src]^T spatial, scatter
// h rows are always 16 floats, 64B-aligned; IC<=16 channels used.
template <int IC>
__global__ void k_edge(const float* __restrict__ hbase,
                       const float* __restrict__ W, const float* __restrict__ b) {
    __shared__ float sW0[IC * HID];
    __shared__ float sW1[IC * HID];
    __shared__ float sB[IC * HID];
    for (int i = threadIdx.x; i < IC * HID; i += blockDim.x) {
        sW0[i] = W[i];
        sW1[i] = W[IC * HID + i];
        sB[i]  = b[i];
    }
    __syncthreads();
    const int M = g_M;
    for (int e = blockIdx.x * blockDim.x + threadIdx.x; e < M;
         e += gridDim.x * blockDim.x) {
        float4 rec = g_aedge[e];                 // single LDG.128 per edge
        int s = __float_as_int(rec.x);
        int d = __float_as_int(rec.y);
        float rx = rec.z, ry = rec.w;
        const float4* h4 = (const float4*)(hbase + (long)s * HID);
        float hv[16];
        float4 v0 = h4[0], v1 = h4[1], v2 = h4[2], v3 = h4[3];
        hv[0] = v0.x; hv[1] = v0.y; hv[2]  = v0.z; hv[3]  = v0.w;
        hv[4] = v1.x; hv[5] = v1.y; hv[6]  = v1.z; hv[7]  = v1.w;
        hv[8] = v2.x; hv[9] = v2.y; hv[10] = v2.z; hv[11] = v2.w;
        hv[12] = v3.x; hv[13] = v3.y; hv[14] = v3.z; hv[15] = v3.w;
        float acc[HID];
#pragma unroll
        for (int j = 0; j < HID; j++) acc[j] = 0.0f;
#pragma unroll
        for (int c = 0; c < IC; c++) {
            float hc = hv[c];
#pragma unroll
            for (int j = 0; j < HID; j++) {
                float sp = fmaf(rx, sW0[c * HID + j],
                            fmaf(ry, sW1[c * HID + j], sB[c * HID + j]));
                sp = fmaxf(sp, 0.0f);
                acc[j] = fmaf(hc, sp, acc[j]);
            }
        }
        float* a = &g_agg[(long)d * HID];
#pragma unroll
        for (int q = 0; q < 4; q++)
            red_add_v4(a + q * 4, acc[q * 4 + 0], acc[q * 4 + 1],
                       acc[q * 4 + 2], acc[q * 4 + 3]);
    }
}

// h_out = relu((agg * cntinv) @ W_out + b_out); re-zero agg for next layer
__global__ void k_node(const float* __restrict__ Wout,
                       const float* __restrict__ bout,
                       float* __restrict__ hout) {
    __shared__ float sW[HID * HID];
    __shared__ float sB[HID];
    for (int i = threadIdx.x; i < HID * HID; i += blockDim.x) sW[i] = Wout[i];
    if (threadIdx.x < HID) sB[threadIdx.x] = bout[threadIdx.x];
    __syncthreads();
    int n = blockIdx.x * blockDim.x + threadIdx.x;
    if (n >= N_NODES) return;
    float inv = g_cntinv[n];
    float a[HID];
    float4* ag = (float4*)&g_agg[(long)n * HID];
    const float4 zero4 = make_float4(0.f, 0.f, 0.f, 0.f);
#pragma unroll
    for (int q = 0; q < 4; q++) {
        float4 v = ag[q];
        a[q * 4 + 0] = v.x * inv;
        a[q * 4 + 1] = v.y * inv;
        a[q * 4 + 2] = v.z * inv;
        a[q * 4 + 3] = v.w * inv;
        ag[q] = zero4;
    }
    float* ho = hout + (long)n * HID;
#pragma unroll
    for (int j = 0; j < HID; j++) {
        float o = sB[j];
#pragma unroll
        for (int k = 0; k < HID; k++) o = fmaf(a[k], sW[k * HID + j], o);
        ho[j] = fmaxf(o, 0.0f);
    }
}

// layer-3 node MLP fused with decoder pre-projection:
// h = relu((agg*inv)@Wout+b); P[n][0:16]=h@Wd1[0:16,:]; P[n][16:32]=h@Wd1[16:32,:]
__global__ void k_node_pre(const float* __restrict__ Wout,
                           const float* __restrict__ bout,
                           const float* __restrict__ Wd1) {
    __shared__ float sW[HID * HID];
    __shared__ float sB[HID];
    __shared__ float sD[32 * HID];
    for (int i = threadIdx.x; i < HID * HID; i += blockDim.x) sW[i] = Wout[i];
    for (int i = threadIdx.x; i < 32 * HID; i += blockDim.x) sD[i] = Wd1[i];
    if (threadIdx.x < HID) sB[threadIdx.x] = bout[threadIdx.x];
    __syncthreads();
    int n = blockIdx.x * blockDim.x + threadIdx.x;
    if (blockIdx.x == 0 && threadIdx.x == 0) g_M = 0;  // reset compaction counter
    if (n >= N_NODES) return;
    float inv = g_cntinv[n];
    float a[HID];
    float4* ag = (float4*)&g_agg[(long)n * HID];
    const float4 zero4 = make_float4(0.f, 0.f, 0.f, 0.f);
#pragma unroll
    for (int q = 0; q < 4; q++) {
        float4 v = ag[q];
        a[q * 4 + 0] = v.x * inv;
        a[q * 4 + 1] = v.y * inv;
        a[q * 4 + 2] = v.z * inv;
        a[q * 4 + 3] = v.w * inv;
        ag[q] = zero4;
    }
    float hres[HID];
#pragma unroll
    for (int j = 0; j < HID; j++) {
        float o = sB[j];
#pragma unroll
        for (int k = 0; k < HID; k++) o = fmaf(a[k], sW[k * HID + j], o);
        hres[j] = fmaxf(o, 0.0f);
    }
    float* P = &g_P[(long)n * 32];
#pragma unroll
    for (int j = 0; j < HID; j++) {
        float t = 0.0f, u = 0.0f;
#pragma unroll
        for (int k = 0; k < HID; k++) {
            t = fmaf(hres[k], sD[k * HID + j], t);           // Wd1 rows 0..15
            u = fmaf(hres[k], sD[(HID + k) * HID + j], u);   // Wd1 rows 16..31
        }
        P[j] = t;
        P[HID + j] = u;
    }
}

// decoder: t1 = relu(Ptop[s] + Pbot[d] + b1); relu MLP; sigmoid
__global__ void k_decoder(const float* __restrict__ bd1,
                          const float* __restrict__ Wd2, const float* __restrict__ bd2,
                          const float* __restrict__ Wd3, const float* __restrict__ bd3,
                          float* __restrict__ out) {
    __shared__ float sB1[HID];
    __shared__ float sW2[HID * HID];
    __shared__ float sB2[HID];
    __shared__ float sW3[HID];
    __shared__ float sB3;
    for (int i = threadIdx.x; i < HID * HID; i += blockDim.x) sW2[i] = Wd2[i];
    if (threadIdx.x < HID) {
        sB1[threadIdx.x] = bd1[threadIdx.x];
        sB2[threadIdx.x] = bd2[threadIdx.x];
        sW3[threadIdx.x] = Wd3[threadIdx.x];
    }
    if (threadIdx.x == 0) sB3 = bd3[0];
    __syncthreads();
    int e = blockIdx.x * blockDim.x + threadIdx.x;
    int2 sd = g_sd[e];                                   // single LDG.64
    const float4* ps = (const float4*)&g_P[(long)sd.x * 32];        // top half
    const float4* pd = (const float4*)&g_P[(long)sd.y * 32 + HID];  // bottom half
    float t1[HID];
#pragma unroll
    for (int q = 0; q < 4; q++) {
        float4 va = ps[q];
        float4 vb = pd[q];
        t1[q * 4 + 0] = fmaxf(va.x + vb.x + sB1[q * 4 + 0], 0.0f);
        t1[q * 4 + 1] = fmaxf(va.y + vb.y + sB1[q * 4 + 1], 0.0f);
        t1[q * 4 + 2] = fmaxf(va.z + vb.z + sB1[q * 4 + 2], 0.0f);
        t1[q * 4 + 3] = fmaxf(va.w + vb.w + sB1[q * 4 + 3], 0.0f);
    }
    float t2[HID];
#pragma unroll
    for (int j = 0; j < HID; j++) {
        float o = sB2[j];
#pragma unroll
        for (int k = 0; k < HID; k++) o = fmaf(t1[k], sW2[k * HID + j], o);
        t2[j] = fmaxf(o, 0.0f);
    }
    float o = sB3;
#pragma unroll
    for (int k = 0; k < HID; k++) o = fmaf(t2[k], sW3[k], o);
    out[e] = 1.0f / (1.0f + __expf(-o));
}

// ---------------- launch ----------------
extern "C" void kernel_launch(void* const* d_in, const int* in_sizes, int n_in,
                              void* d_out, int out_size) {
    const float* x      = (const float*)d_in[0];
    const int*   ei     = (const int*)d_in[1];
    const int*   region = (const int*)d_in[2];
    const float* W_in1  = (const float*)d_in[3];
    const float* b_in1  = (const float*)d_in[4];
    const float* W_out1 = (const float*)d_in[5];
    const float* b_out1 = (const float*)d_in[6];
    const float* W_in2  = (const float*)d_in[7];
    const float* b_in2  = (const float*)d_in[8];
    const float* W_out2 = (const float*)d_in[9];
    const float* b_out2 = (const float*)d_in[10];
    const float* W_in3  = (const float*)d_in[11];
    const float* b_in3  = (const float*)d_in[12];
    const float* W_out3 = (const float*)d_in[13];
    const float* b_out3 = (const float*)d_in[14];
    const float* Wd1 = (const float*)d_in[15];
    const float* bd1 = (const float*)d_in[16];
    const float* Wd2 = (const float*)d_in[17];
    const float* bd2 = (const float*)d_in[18];
    const float* Wd3 = (const float*)d_in[19];
    const float* bd3 = (const float*)d_in[20];
    float* out = (float*)d_out;

    float *hin, *h0, *h1;
    cudaGetSymbolAddress((void**)&hin, g_hin);
    cudaGetSymbolAddress((void**)&h0, g_h0);
    cudaGetSymbolAddress((void**)&h1, g_h1);

    const int TB = 256;
    const int gN   = (N_NODES + TB - 1) / TB;
    const int gE   = N_EDGES / TB;          // exact: 800000/256 = 3125
    const int gEdge = 592;                  // grid-stride over active edges

    k_detect<<<1, 32>>>(ei, region);
    k_setup<<<gE, TB>>>(ei, region, x);
    k_cntinv<<<gN, TB>>>(x);

    // layer 1: staged features in g_hin (14 channels, rows padded to 16)
    k_edge<14><<<gEdge, TB>>>(hin, W_in1, b_in1);
    k_node<<<gN, TB>>>(W_out1, b_out1, h0);

    // layer 2
    k_edge<16><<<gEdge, TB>>>(h0, W_in2, b_in2);
    k_node<<<gN, TB>>>(W_out2, b_out2, h1);

    // layer 3 fused with decoder pre-projection
    k_edge<16><<<gEdge, TB>>>(h1, W_in3, b_in3);
    k_node_pre<<<gN, TB>>>(W_out3, b_out3, Wd1);

    // decoder
    k_decoder<<<gE, TB>>>(bd1, Wd2, bd2, Wd3, bd3, out);
}

// round 13
// speedup vs baseline: 1.2028x; 1.0121x over previous
#include <cuda_runtime.h>
#include <cuda_bf16.h>
#include <math.h>

#define N_NODES 50000
#define N_EDGES 800000
#define HID 16

typedef unsigned long long ull;

// ---------------- device scratch (zero-initialized at module load) ----------------
__device__ int2   g_sd[N_EDGES];                         // packed (src,dst) for decoder
__device__ __align__(16) float4 g_aedge[N_EDGES];        // packed active edge {s,d,rx,ry}
__device__ int    g_M;
__device__ int    g_cnt[N_NODES];          // invariant: zero at launch entry
__device__ float  g_cntinv[N_NODES];
__device__ __align__(16) float g_hin[N_NODES * HID];     // staged layer-1 features
__device__ __align__(16) float g_h0[N_NODES * HID];
__device__ __align__(16) float g_h1[N_NODES * HID];
__device__ __align__(16) float g_agg[N_NODES * HID];     // invariant: zero at entry
__device__ __align__(16) float g_P[N_NODES * 32];        // per-node decoder projections
__device__ int    g_is64_ei;
__device__ int    g_is64_rg;

// ---------------- packed f32x2 helpers (sm_103a) ----------------
__device__ __forceinline__ ull fma2(ull a, ull b, ull c) {
    ull d; asm("fma.rn.f32x2 %0, %1, %2, %3;" : "=l"(d) : "l"(a), "l"(b), "l"(c));
    return d;
}
__device__ __forceinline__ ull add2(ull a, ull b) {
    ull d; asm("add.rn.f32x2 %0, %1, %2;" : "=l"(d) : "l"(a), "l"(b));
    return d;
}
__device__ __forceinline__ ull pk(float lo, float hi) {
    ull r; asm("mov.b64 %0, {%1, %2};" : "=l"(r) : "f"(lo), "f"(hi)); return r;
}
__device__ __forceinline__ void upk(ull v, float& lo, float& hi) {
    asm("mov.b64 {%0, %1}, %2;" : "=f"(lo), "=f"(hi) : "l"(v));
}

// ---------------- kernels ----------------

// detect int64 vs int32 layout
__global__ void k_detect(const int* __restrict__ ei, const int* __restrict__ rg) {
    if (blockIdx.x == 0 && threadIdx.x == 0) {
        int all0 = 1;
        for (int i = 0; i < 32; i++) if (ei[2 * i + 1] != 0) { all0 = 0; break; }
        g_is64_ei = all0;
        all0 = 1;
        for (int i = 0; i < 32; i++) if (rg[2 * i + 1] != 0) { all0 = 0; break; }
        g_is64_rg = all0;
    }
}

// count in-degree, compact same-region edges (warp-aggregated counter) + rel
__global__ void k_setup(const int* __restrict__ ei,
                        const int* __restrict__ region,
                        const float* __restrict__ x) {
    int e = blockIdx.x * blockDim.x + threadIdx.x;   // grid sized exactly
    int is64e = g_is64_ei;
    int is64r = g_is64_rg;
    int s, d;
    if (is64e) { s = ei[2 * e]; d = ei[2 * (N_EDGES + e)]; }
    else       { s = ei[e];     d = ei[N_EDGES + e]; }
    g_sd[e] = make_int2(s, d);
    atomicAdd(&g_cnt[d], 1);
    int rs = is64r ? region[2 * s] : region[s];
    int rd = is64r ? region[2 * d] : region[d];
    bool active = (rs == rd);
    unsigned mask = __ballot_sync(0xffffffffu, active);
    if (active) {
        int lane = threadIdx.x & 31;
        int leader = __ffs(mask) - 1;
        int base = 0;
        if (lane == leader) base = atomicAdd(&g_M, __popc(mask));
        base = __shfl_sync(mask, base, leader);
        int i = base + __popc(mask & ((1u << lane) - 1u));
        float4 rec;
        rec.x = __int_as_float(s);
        rec.y = __int_as_float(d);
        rec.z = x[d * 16 + 0] - x[s * 16 + 0];
        rec.w = x[d * 16 + 1] - x[s * 16 + 1];
        g_aedge[i] = rec;
    }
}

// cnt -> 1/max(cnt,1) (restore cnt=0), and stage layer-1 features
__global__ void k_cntinv(const float* __restrict__ x) {
    int n = blockIdx.x * blockDim.x + threadIdx.x;
    if (n >= N_NODES) return;
    g_cntinv[n] = 1.0f / fmaxf((float)g_cnt[n], 1.0f);
    g_cnt[n] = 0;
    const float4* xr = (const float4*)(x + (long)n * 16);
    float4 v0 = xr[0], v1 = xr[1], v2 = xr[2], v3 = xr[3];
    float4* ho = (float4*)&g_hin[(long)n * HID];
    ho[0] = make_float4(v0.z, v0.w, v1.x, v1.y);
    ho[1] = make_float4(v1.z, v1.w, v2.x, v2.y);
    ho[2] = make_float4(v2.z, v2.w, v3.x, v3.y);
    ho[3] = make_float4(v3.z, v3.w, 0.0f, 0.0f);
}

__device__ __forceinline__ void red_add_v4(float* p, float a, float b, float c, float d) {
    asm volatile("red.global.add.v4.f32 [%0], {%1, %2, %3, %4};"
                 :: "l"(p), "f"(a), "f"(b), "f"(c), "f"(d) : "memory");
}

// per active edge: spatial = relu(rel@W_in+b_in), msg = h[src]^T spatial, scatter
// packed f32x2 over j-pairs; interleaved weight layout in shared.
template <int IC>
__global__ void k_edge(const float* __restrict__ hbase,
                       const float* __restrict__ W, const float* __restrict__ b) {
    __shared__ float4 sW4[IC * 8];   // {W0[c][2p], W0[c][2p+1], W1[c][2p], W1[c][2p+1]}
    __shared__ float2 sB2[IC * 8];   // {B[c][2p], B[c][2p+1]}
    for (int i = threadIdx.x; i < IC * 8; i += blockDim.x) {
        int c = i >> 3, p = i & 7;
        sW4[i] = make_float4(W[c * 16 + 2 * p], W[c * 16 + 2 * p + 1],
                             W[IC * 16 + c * 16 + 2 * p], W[IC * 16 + c * 16 + 2 * p + 1]);
        sB2[i] = make_float2(b[c * 16 + 2 * p], b[c * 16 + 2 * p + 1]);
    }
    __syncthreads();
    const int M = g_M;
    for (int e = blockIdx.x * blockDim.x + threadIdx.x; e < M;
         e += gridDim.x * blockDim.x) {
        float4 rec = g_aedge[e];                 // single LDG.128 per edge
        int s = __float_as_int(rec.x);
        int d = __float_as_int(rec.y);
        ull rx2 = pk(rec.z, rec.z);
        ull ry2 = pk(rec.w, rec.w);
        const float4* h4 = (const float4*)(hbase + (long)s * HID);
        float hv[16];
        float4 v0 = h4[0], v1 = h4[1], v2 = h4[2], v3 = h4[3];
        hv[0] = v0.x; hv[1] = v0.y; hv[2]  = v0.z; hv[3]  = v0.w;
        hv[4] = v1.x; hv[5] = v1.y; hv[6]  = v1.z; hv[7]  = v1.w;
        hv[8] = v2.x; hv[9] = v2.y; hv[10] = v2.z; hv[11] = v2.w;
        hv[12] = v3.x; hv[13] = v3.y; hv[14] = v3.z; hv[15] = v3.w;
        ull acc2[8];
#pragma unroll
        for (int p = 0; p < 8; p++) acc2[p] = pk(0.0f, 0.0f);
#pragma unroll
        for (int c = 0; c < IC; c++) {
            ull hc2 = pk(hv[c], hv[c]);
#pragma unroll
            for (int p = 0; p < 8; p++) {
                float4 w = sW4[c * 8 + p];       // LDS.128
                float2 bb = sB2[c * 8 + p];      // LDS.64
                ull t = fma2(ry2, pk(w.z, w.w), pk(bb.x, bb.y));
                t = fma2(rx2, pk(w.x, w.y), t);
                float lo, hi; upk(t, lo, hi);
                lo = fmaxf(lo, 0.0f);
                hi = fmaxf(hi, 0.0f);
                acc2[p] = fma2(hc2, pk(lo, hi), acc2[p]);
            }
        }
        float a[16];
#pragma unroll
        for (int p = 0; p < 8; p++) upk(acc2[p], a[2 * p], a[2 * p + 1]);
        float* ag = &g_agg[(long)d * HID];
#pragma unroll
        for (int q = 0; q < 4; q++)
            red_add_v4(ag + q * 4, a[q * 4 + 0], a[q * 4 + 1],
                       a[q * 4 + 2], a[q * 4 + 3]);
    }
}

// h_out = relu((agg * cntinv) @ W_out + b_out); re-zero agg for next layer
__global__ void k_node(const float* __restrict__ Wout,
                       const float* __restrict__ bout,
                       float* __restrict__ hout) {
    __shared__ float sW[HID * HID];
    __shared__ float sB[HID];
    for (int i = threadIdx.x; i < HID * HID; i += blockDim.x) sW[i] = Wout[i];
    if (threadIdx.x < HID) sB[threadIdx.x] = bout[threadIdx.x];
    __syncthreads();
    int n = blockIdx.x * blockDim.x + threadIdx.x;
    if (n >= N_NODES) return;
    float inv = g_cntinv[n];
    float a[HID];
    float4* ag = (float4*)&g_agg[(long)n * HID];
    const float4 zero4 = make_float4(0.f, 0.f, 0.f, 0.f);
#pragma unroll
    for (int q = 0; q < 4; q++) {
        float4 v = ag[q];
        a[q * 4 + 0] = v.x * inv;
        a[q * 4 + 1] = v.y * inv;
        a[q * 4 + 2] = v.z * inv;
        a[q * 4 + 3] = v.w * inv;
        ag[q] = zero4;
    }
    float* ho = hout + (long)n * HID;
#pragma unroll
    for (int j = 0; j < HID; j++) {
        float o = sB[j];
#pragma unroll
        for (int k = 0; k < HID; k++) o = fmaf(a[k], sW[k * HID + j], o);
        ho[j] = fmaxf(o, 0.0f);
    }
}

// layer-3 node MLP fused with decoder pre-projection
__global__ void k_node_pre(const float* __restrict__ Wout,
                           const float* __restrict__ bout,
                           const float* __restrict__ Wd1) {
    __shared__ float sW[HID * HID];
    __shared__ float sB[HID];
    __shared__ float sD[32 * HID];
    for (int i = threadIdx.x; i < HID * HID; i += blockDim.x) sW[i] = Wout[i];
    for (int i = threadIdx.x; i < 32 * HID; i += blockDim.x) sD[i] = Wd1[i];
    if (threadIdx.x < HID) sB[threadIdx.x] = bout[threadIdx.x];
    __syncthreads();
    int n = blockIdx.x * blockDim.x + threadIdx.x;
    if (blockIdx.x == 0 && threadIdx.x == 0) g_M = 0;  // reset compaction counter
    if (n >= N_NODES) return;
    float inv = g_cntinv[n];
    float a[HID];
    float4* ag = (float4*)&g_agg[(long)n * HID];
    const float4 zero4 = make_float4(0.f, 0.f, 0.f, 0.f);
#pragma unroll
    for (int q = 0; q < 4; q++) {
        float4 v = ag[q];
        a[q * 4 + 0] = v.x * inv;
        a[q * 4 + 1] = v.y * inv;
        a[q * 4 + 2] = v.z * inv;
        a[q * 4 + 3] = v.w * inv;
        ag[q] = zero4;
    }
    float hres[HID];
#pragma unroll
    for (int j = 0; j < HID; j++) {
        float o = sB[j];
#pragma unroll
        for (int k = 0; k < HID; k++) o = fmaf(a[k], sW[k * HID + j], o);
        hres[j] = fmaxf(o, 0.0f);
    }
    float* P = &g_P[(long)n * 32];
#pragma unroll
    for (int j = 0; j < HID; j++) {
        float t = 0.0f, u = 0.0f;
#pragma unroll
        for (int k = 0; k < HID; k++) {
            t = fmaf(hres[k], sD[k * HID + j], t);           // Wd1 rows 0..15
            u = fmaf(hres[k], sD[(HID + k) * HID + j], u);   // Wd1 rows 16..31
        }
        P[j] = t;
        P[HID + j] = u;
    }
}

// decoder: t1 = relu(Ptop[s] + Pbot[d] + b1); relu MLP (packed f32x2); sigmoid
__global__ void k_decoder(const float* __restrict__ bd1,
                          const float* __restrict__ Wd2, const float* __restrict__ bd2,
                          const float* __restrict__ Wd3, const float* __restrict__ bd3,
                          float* __restrict__ out) {
    __shared__ float2 sB1p[8];
    __shared__ float2 sW2p[HID * 8];   // W2[k] j-pairs
    __shared__ float2 sB2p[8];
    __shared__ float2 sW3p[8];
    __shared__ float sB3;
    for (int i = threadIdx.x; i < HID * 8; i += blockDim.x) {
        int k = i >> 3, p = i & 7;
        sW2p[i] = make_float2(Wd2[k * HID + 2 * p], Wd2[k * HID + 2 * p + 1]);
    }
    if (threadIdx.x < 8) {
        sB1p[threadIdx.x] = make_float2(bd1[2 * threadIdx.x], bd1[2 * threadIdx.x + 1]);
        sB2p[threadIdx.x] = make_float2(bd2[2 * threadIdx.x], bd2[2 * threadIdx.x + 1]);
        sW3p[threadIdx.x] = make_float2(Wd3[2 * threadIdx.x], Wd3[2 * threadIdx.x + 1]);
    }
    if (threadIdx.x == 0) sB3 = bd3[0];
    __syncthreads();
    int e = blockIdx.x * blockDim.x + threadIdx.x;
    int2 sd = g_sd[e];                                   // single LDG.64
    const float4* ps = (const float4*)&g_P[(long)sd.x * 32];        // top half
    const float4* pd = (const float4*)&g_P[(long)sd.y * 32 + HID];  // bottom half
    float t1[HID];
#pragma unroll
    for (int q = 0; q < 4; q++) {
        float4 va = ps[q];
        float4 vb = pd[q];
        float2 b0 = sB1p[2 * q], b1 = sB1p[2 * q + 1];
        ull u0 = add2(add2(pk(va.x, va.y), pk(vb.x, vb.y)), pk(b0.x, b0.y));
        ull u1 = add2(add2(pk(va.z, va.w), pk(vb.z, vb.w)), pk(b1.x, b1.y));
        float l0, h0, l1, h1;
        upk(u0, l0, h0); upk(u1, l1, h1);
        t1[q * 4 + 0] = fmaxf(l0, 0.0f);
        t1[q * 4 + 1] = fmaxf(h0, 0.0f);
        t1[q * 4 + 2] = fmaxf(l1, 0.0f);
        t1[q * 4 + 3] = fmaxf(h1, 0.0f);
    }
    // t2 pairs = relu(b2p + sum_k t1[k] * W2p[k])
    ull t2p[8];
#pragma unroll
    for (int p = 0; p < 8; p++) {
        float2 bb = sB2p[p];
        t2p[p] = pk(bb.x, bb.y);
    }
#pragma unroll
    for (int k = 0; k < HID; k++) {
        ull tk2 = pk(t1[k], t1[k]);
#pragma unroll
        for (int p = 0; p < 8; p++) {
            float2 w = sW2p[k * 8 + p];
            t2p[p] = fma2(tk2, pk(w.x, w.y), t2p[p]);
        }
    }
    // t3 = b3 + sum relu(t2) * W3  (packed accumulate, then horizontal)
    ull acc = pk(0.0f, 0.0f);
#pragma unroll
    for (int p = 0; p < 8; p++) {
        float lo, hi; upk(t2p[p], lo, hi);
        lo = fmaxf(lo, 0.0f);
        hi = fmaxf(hi, 0.0f);
        float2 w = sW3p[p];
        acc = fma2(pk(lo, hi), pk(w.x, w.y), acc);
    }
    float alo, ahi; upk(acc, alo, ahi);
    float o = sB3 + alo + ahi;
    out[e] = 1.0f / (1.0f + __expf(-o));
}

// ---------------- launch ----------------
extern "C" void kernel_launch(void* const* d_in, const int* in_sizes, int n_in,
                              void* d_out, int out_size) {
    const float* x      = (const float*)d_in[0];
    const int*   ei     = (const int*)d_in[1];
    const int*   region = (const int*)d_in[2];
    const float* W_in1  = (const float*)d_in[3];
    const float* b_in1  = (const float*)d_in[4];
    const float* W_out1 = (const float*)d_in[5];
    const float* b_out1 = (const float*)d_in[6];
    const float* W_in2  = (const float*)d_in[7];
    const float* b_in2  = (const float*)d_in[8];
    const float* W_out2 = (const float*)d_in[9];
    const float* b_out2 = (const float*)d_in[10];
    const float* W_in3  = (const float*)d_in[11];
    const float* b_in3  = (const float*)d_in[12];
    const float* W_out3 = (const float*)d_in[13];
    const float* b_out3 = (const float*)d_in[14];
    const float* Wd1 = (const float*)d_in[15];
    const float* bd1 = (const float*)d_in[16];
    const float* Wd2 = (const float*)d_in[17];
    const float* bd2 = (const float*)d_in[18];
    const float* Wd3 = (const float*)d_in[19];
    const float* bd3 = (const float*)d_in[20];
    float* out = (float*)d_out;

    float *hin, *h0, *h1;
    cudaGetSymbolAddress((void**)&hin, g_hin);
    cudaGetSymbolAddress((void**)&h0, g_h0);
    cudaGetSymbolAddress((void**)&h1, g_h1);

    const int TB = 256;
    const int gN   = (N_NODES + TB - 1) / TB;
    const int gE   = N_EDGES / TB;          // exact: 800000/256 = 3125
    const int gEdge = 592;                  // grid-stride over active edges

    k_detect<<<1, 32>>>(ei, region);
    k_setup<<<gE, TB>>>(ei, region, x);
    k_cntinv<<<gN, TB>>>(x);

    // layer 1: staged features in g_hin (14 channels, rows padded to 16)
    k_edge<14><<<gEdge, TB>>>(hin, W_in1, b_in1);
    k_node<<<gN, TB>>>(W_out1, b_out1, h0);

    // layer 2
    k_edge<16><<<gEdge, TB>>>(h0, W_in2, b_in2);
    k_node<<<gN, TB>>>(W_out2, b_out2, h1);

    // layer 3 fused with decoder pre-projection
    k_edge<16><<<gEdge, TB>>>(h1, W_in3, b_in3);
    k_node_pre<<<gN, TB>>>(W_out3, b_out3, Wd1);

    // decoder
    k_decoder<<<gE, TB>>>(bd1, Wd2, bd2, Wd3, bd3, out);
}